// round 3
// baseline (speedup 1.0000x reference)
#include <cuda_runtime.h>
#include <math.h>
#include <stdint.h>

#define B_   128
#define S_   32
#define IN_  512
#define H_   1024
#define OUT_ 512
#define NMEM 16384
#define WMEM 128
#define CDIM 899
#define G4H  4096
#define CP   1028
#define WF_M 1152
#define WF_K 912

// ---------------- scratch ----------------
__device__ float g_mem [NMEM*WMEM];
__device__ float g_mhat[NMEM*WMEM];
__device__ float g_h   [B_*H_];
__device__ float g_c   [B_*H_];
__device__ float g_rv  [B_*WMEM];
__device__ float g_rw  [B_*NMEM];
__device__ float g_ww  [B_*NMEM];
__device__ float g_gates[B_*G4H];
__device__ float g_P   [B_*CP];
__device__ float g_khat[2*B_*WMEM];
__device__ float g_gamma[2*B_];
__device__ float g_er  [B_*WMEM];
__device__ float g_ad  [B_*WMEM];
__device__ float g_sim [2*B_*NMEM];
__device__ float g_bsum[G4H];
__device__ float g_HWcat[WF_M*WF_K];
__device__ float g_WoutT[H_*WF_K];
__device__ float g_Wf  [WF_M*H_];
__device__ float g_bf  [CP];

__device__ __forceinline__ float sigmoidf_(float x){ return 1.f/(1.f+__expf(-x)); }
__device__ __forceinline__ float softplusf_(float x){ return x>20.f ? x : log1pf(__expf(x)); }

// ============ generic NT GEMM: C[m,n] (+)= sum_k A[m,k]*B[n,k] ============
// A: up to 3 row-major segments along k; B: up to 2. All segment boundaries
// are multiples of 16 so BK tiles never straddle. MODE 0 overwrite (+bias),
// MODE 2 atomicAdd (C preinitialized).
template<int MODE>
__global__ void __launch_bounds__(256) gemm_nt(
    const float* __restrict__ A0,int alda0,int alen0,
    const float* __restrict__ A1,int alda1,int alen1,
    const float* __restrict__ A2,int alda2,
    const float* __restrict__ B0,int blda0,int blen0,
    const float* __restrict__ B1,int blda1,
    float* __restrict__ C,int ldc,int Nn,
    int ktotal,int ktPerZ,
    const float* __restrict__ bias)
{
    __shared__ __align__(16) float As[16][132];
    __shared__ __align__(16) float Bs[16][68];
    int tid = threadIdx.x;
    int tx = tid & 15, ty = tid >> 4;
    int n0 = blockIdx.x*64, m0 = blockIdx.y*128;
    int kb = blockIdx.z*ktPerZ;
    int ke = kb + ktPerZ; if (ke > ktotal) ke = ktotal;

    float acc[8][4];
#pragma unroll
    for (int i=0;i<8;++i)
#pragma unroll
        for (int j=0;j<4;++j) acc[i][j]=0.f;

    for (int kt=kb; kt<ke; ++kt) {
        int kk0 = kt*16;
        const float* Ap; int alda, ak;
        if      (kk0 <  alen0)       { Ap=A0; alda=alda0; ak=kk0; }
        else if (kk0 <  alen0+alen1) { Ap=A1; alda=alda1; ak=kk0-alen0; }
        else                         { Ap=A2; alda=alda2; ak=kk0-alen0-alen1; }
        const float* Bp; int blda, bk;
        if (kk0 < blen0) { Bp=B0; blda=blda0; bk=kk0; }
        else             { Bp=B1; blda=blda1; bk=kk0-blen0; }

#pragma unroll
        for (int i=0;i<8;++i) {              // 128x16 A tile
            int l = tid + i*256; int m = l>>4, k = l&15;
            As[k][m] = Ap[(size_t)(m0+m)*alda + ak + k];
        }
#pragma unroll
        for (int i=0;i<4;++i) {              // 64x16 B tile
            int l = tid + i*256; int n = l>>4, k = l&15;
            Bs[k][n] = (n0+n < Nn) ? Bp[(size_t)(n0+n)*blda + bk + k] : 0.f;
        }
        __syncthreads();
#pragma unroll
        for (int k=0;k<16;++k) {
            float4 a0 = *reinterpret_cast<const float4*>(&As[k][ty*8]);
            float4 a1 = *reinterpret_cast<const float4*>(&As[k][ty*8+4]);
            float4 b0 = *reinterpret_cast<const float4*>(&Bs[k][tx*4]);
            float ar[8] = {a0.x,a0.y,a0.z,a0.w,a1.x,a1.y,a1.z,a1.w};
            float br[4] = {b0.x,b0.y,b0.z,b0.w};
#pragma unroll
            for (int i=0;i<8;++i)
#pragma unroll
                for (int j=0;j<4;++j) acc[i][j]=fmaf(ar[i],br[j],acc[i][j]);
        }
        __syncthreads();
    }
#pragma unroll
    for (int i=0;i<8;++i) {
        int m = m0 + ty*8 + i;
#pragma unroll
        for (int j=0;j<4;++j) {
            int n = n0 + tx*4 + j;
            if (n < Nn) {
                size_t idx = (size_t)m*ldc + n;
                if (MODE==0) C[idx] = acc[i][j] + (bias ? bias[n] : 0.f);
                else         atomicAdd(&C[idx], acc[i][j]);
            }
        }
    }
}

// ---------------- preamble ----------------
__global__ void init_state() {
    int idx = blockIdx.x*256 + threadIdx.x;          // B_*NMEM threads
    g_rw[idx] = 1.f/NMEM;
    if (idx < B_*H_)   { g_h[idx]=0.f; g_c[idx]=0.f; }
    if (idx < B_*WMEM)   g_rv[idx]=0.f;
}
__global__ void bsum_k(const float* __restrict__ bih, const float* __restrict__ bhh) {
    int i = blockIdx.x*256 + threadIdx.x;
    if (i < G4H) g_bsum[i] = bih[i]+bhh[i];
}
__global__ void gather_HWcat(
    const float* __restrict__ rkW, const float* __restrict__ rbW, const float* __restrict__ rgW,
    const float* __restrict__ wkW, const float* __restrict__ wbW, const float* __restrict__ wgW,
    const float* __restrict__ erW, const float* __restrict__ adW, const float* __restrict__ pW)
{
    int idx = blockIdx.x*256 + threadIdx.x;          // WF_M*WF_K exact
    int j = idx / WF_K, cx = idx % WF_K;
    float v = 0.f;
    if (cx < CDIM) {
        if      (j < 128)  v = rkW[(size_t)j*CDIM + cx];
        else if (j == 128) v = rbW[cx];
        else if (j == 129) v = rgW[cx];
        else if (j < 258)  v = wkW[(size_t)(j-130)*CDIM + cx];
        else if (j == 258) v = wbW[cx];
        else if (j == 259) v = wgW[cx];
        else if (j < 388)  v = erW[(size_t)(j-260)*CDIM + cx];
        else if (j < 516)  v = adW[(size_t)(j-388)*CDIM + cx];
        else if (j < CP)   { if (cx < OUT_) v = pW[(size_t)(j-516)*OUT_ + cx]; }
    }
    g_HWcat[idx] = v;
}
__global__ void transpose_Wout(const float* __restrict__ Wout) {
    int idx = blockIdx.x*256 + threadIdx.x;          // H_*WF_K exact
    int h = idx / WF_K, c = idx % WF_K;
    g_WoutT[idx] = (c < CDIM) ? Wout[(size_t)c*H_ + h] : 0.f;
}
__global__ void __launch_bounds__(128) bf_k(
    const float* __restrict__ bout,
    const float* __restrict__ rkb, const float* __restrict__ rbb, const float* __restrict__ rgb,
    const float* __restrict__ wkb, const float* __restrict__ wbb, const float* __restrict__ wgb,
    const float* __restrict__ erb, const float* __restrict__ adb, const float* __restrict__ pb)
{
    int j = blockIdx.x, tid = threadIdx.x;
    float s = 0.f;
    for (int c = tid; c < CDIM; c += 128) s += g_HWcat[(size_t)j*WF_K + c] * bout[c];
#pragma unroll
    for (int o=16;o;o>>=1) s += __shfl_xor_sync(0xffffffffu, s, o);
    __shared__ float red[4];
    if ((tid&31)==0) red[tid>>5] = s;
    __syncthreads();
    if (tid==0) {
        float t = red[0]+red[1]+red[2]+red[3], hb;
        if      (j < 128)  hb = rkb[j];
        else if (j == 128) hb = rbb[0];
        else if (j == 129) hb = rgb[0];
        else if (j < 258)  hb = wkb[j-130];
        else if (j == 258) hb = wbb[0];
        else if (j == 259) hb = wgb[0];
        else if (j < 388)  hb = erb[j-260];
        else if (j < 516)  hb = adb[j-388];
        else               hb = pb[j-516];
        g_bf[j] = t + hb;
    }
}
__global__ void __launch_bounds__(256) norm_mhat(const float* __restrict__ memin) {
    int warp = threadIdx.x>>5, lane = threadIdx.x&31;
    int r = blockIdx.x*8 + warp;
    float v[4]; float ss = 0.f;
#pragma unroll
    for (int i=0;i<4;++i) { v[i] = memin[(size_t)r*WMEM + lane + 32*i]; ss += v[i]*v[i]; }
#pragma unroll
    for (int o=16;o;o>>=1) ss += __shfl_xor_sync(0xffffffffu, ss, o);
    float inv = 1.f/fmaxf(sqrtf(ss), 1e-12f);
#pragma unroll
    for (int i=0;i<4;++i) {
        g_mem [(size_t)r*WMEM + lane + 32*i] = v[i];
        g_mhat[(size_t)r*WMEM + lane + 32*i] = v[i]*inv;
    }
}

// ---------------- per-step ----------------
__global__ void preinit_gates() {
    int idx = blockIdx.x*256 + threadIdx.x;          // B_*G4H exact
    g_gates[idx] = g_bsum[idx & (G4H-1)];
}
__global__ void __launch_bounds__(256) lstm_pw() {
    int idx = blockIdx.x*256 + threadIdx.x;          // B_*H_ exact
    int b = idx >> 10, j = idx & 1023;
    const float* g = g_gates + (size_t)b*G4H;
    float i_ = g[j], f_ = g[j+1024], gg = g[j+2048], o_ = g[j+3072];
    float cv = g_c[idx];
    cv = sigmoidf_(f_)*cv + sigmoidf_(i_)*tanhf(gg);
    g_c[idx] = cv;
    g_h[idx] = sigmoidf_(o_)*tanhf(cv);
}
__global__ void preinit_P() {
    int idx = blockIdx.x*256 + threadIdx.x;
    if (idx < B_*CP) g_P[idx] = g_bf[idx % CP];
}
__global__ void __launch_bounds__(128) head_pw(float* __restrict__ out, int t) {
    int b = blockIdx.x, tid = threadIdx.x;
    const float* p = g_P + (size_t)b*CP;
    __shared__ float red[4];
    __shared__ float bnr, bnw;
    float rk = p[tid], wk = p[130+tid];
    float s = rk*rk;
#pragma unroll
    for (int o=16;o;o>>=1) s += __shfl_xor_sync(0xffffffffu, s, o);
    if ((tid&31)==0) red[tid>>5] = s;
    __syncthreads();
    if (tid==0) bnr = sqrtf(red[0]+red[1]+red[2]+red[3]);
    __syncthreads();
    s = wk*wk;
#pragma unroll
    for (int o=16;o;o>>=1) s += __shfl_xor_sync(0xffffffffu, s, o);
    if ((tid&31)==0) red[tid>>5] = s;
    __syncthreads();
    if (tid==0) bnw = sqrtf(red[0]+red[1]+red[2]+red[3]);
    __syncthreads();

    float rbeta = softplusf_(p[128]);
    float wbeta = softplusf_(p[258]);
    g_khat[(size_t)b*WMEM + tid]      = rbeta * rk / fmaxf(bnr, 1e-12f);
    g_khat[(size_t)(B_+b)*WMEM + tid] = wbeta * wk / fmaxf(bnw, 1e-12f);
    if (tid==0) {
        g_gamma[b]    = 1.f + softplusf_(p[129]);
        g_gamma[B_+b] = 1.f + softplusf_(p[259]);
    }
    g_er[(size_t)b*WMEM + tid] = sigmoidf_(p[260+tid]);
    g_ad[(size_t)b*WMEM + tid] = tanhf(p[388+tid]);
#pragma unroll
    for (int j=tid; j<OUT_; j+=128)
        out[((size_t)b*S_ + t)*OUT_ + j] = p[516+j];
}
__global__ void __launch_bounds__(256) softmax_interp() {
    int row = blockIdx.x, tid = threadIdx.x;
    const float* sr = g_sim + (size_t)row*NMEM;
    __shared__ float red[8];
    __shared__ float bmax, bsum2;
    float mx = -3.4e38f;
    for (int n=tid; n<NMEM; n+=256) mx = fmaxf(mx, sr[n]);
#pragma unroll
    for (int o=16;o;o>>=1) mx = fmaxf(mx, __shfl_xor_sync(0xffffffffu, mx, o));
    if ((tid&31)==0) red[tid>>5] = mx;
    __syncthreads();
    if (tid==0) { float t=red[0]; for (int i=1;i<8;++i) t=fmaxf(t,red[i]); bmax=t; }
    __syncthreads();
    float sum = 0.f;
    for (int n=tid; n<NMEM; n+=256) sum += __expf(sr[n]-bmax);
#pragma unroll
    for (int o=16;o;o>>=1) sum += __shfl_xor_sync(0xffffffffu, sum, o);
    if ((tid&31)==0) red[tid>>5] = sum;
    __syncthreads();
    if (tid==0) { float t=0.f; for (int i=0;i<8;++i) t+=red[i]; bsum2=t; }
    __syncthreads();
    float inv = 1.f/bsum2;
    float g = g_gamma[row];
    if (row < B_) {
        float* dst = g_rw + (size_t)row*NMEM;
        for (int n=tid; n<NMEM; n+=256) {
            float w = __expf(sr[n]-bmax)*inv;
            dst[n] = g*w + (1.f-g)*dst[n];
        }
    } else {
        float* dst = g_ww + (size_t)(row-B_)*NMEM;
        const float u = 1.f/NMEM;
        for (int n=tid; n<NMEM; n+=256) {
            float w = __expf(sr[n]-bmax)*inv;
            dst[n] = g*w + (1.f-g)*u;
        }
    }
}
// erase/add GEMMs + mem update + renorm (mhat). Block = 32 mem rows x 128 w.
__global__ void __launch_bounds__(256) mem_write() {
    __shared__ float wws[32][33];
    __shared__ __align__(16) float4 ers4[32][32];
    __shared__ __align__(16) float4 ads4[32][32];
    int tid = threadIdx.x;
    int nl = tid>>3, wq = tid&7;
    int nb = blockIdx.x*32;
    float accE[16], accA[16];
#pragma unroll
    for (int j=0;j<16;++j){accE[j]=0.f;accA[j]=0.f;}
    for (int bc=0; bc<4; ++bc) {
        int b0 = bc*32;
#pragma unroll
        for (int i=0;i<4;++i) {
            int l = tid + i*256; int bb = l>>5, nn = l&31;
            wws[bb][nn] = g_ww[(size_t)(b0+bb)*NMEM + nb + nn];
        }
#pragma unroll
        for (int i=0;i<4;++i) {
            int l = tid + i*256; int bb = l>>5, w4 = l&31;
            ers4[bb][w4] = reinterpret_cast<const float4*>(g_er)[(size_t)(b0+bb)*32 + w4];
            ads4[bb][w4] = reinterpret_cast<const float4*>(g_ad)[(size_t)(b0+bb)*32 + w4];
        }
        __syncthreads();
#pragma unroll 4
        for (int bb=0; bb<32; ++bb) {
            float wv = wws[bb][nl];
#pragma unroll
            for (int q=0;q<4;++q) {
                float4 e = ers4[bb][wq*4+q];
                float4 a = ads4[bb][wq*4+q];
                accE[q*4+0]=fmaf(wv,e.x,accE[q*4+0]); accA[q*4+0]=fmaf(wv,a.x,accA[q*4+0]);
                accE[q*4+1]=fmaf(wv,e.y,accE[q*4+1]); accA[q*4+1]=fmaf(wv,a.y,accA[q*4+1]);
                accE[q*4+2]=fmaf(wv,e.z,accE[q*4+2]); accA[q*4+2]=fmaf(wv,a.z,accA[q*4+2]);
                accE[q*4+3]=fmaf(wv,e.w,accE[q*4+3]); accA[q*4+3]=fmaf(wv,a.w,accA[q*4+3]);
            }
        }
        __syncthreads();
    }
    int n = nb + nl;
    float nv[16]; float ss = 0.f;
#pragma unroll
    for (int j=0;j<16;++j) {
        int w = wq*16 + j;
        float m = g_mem[(size_t)n*WMEM + w];
        float v = m*(1.f-accE[j]) + accA[j];
        nv[j] = v; ss += v*v;
        g_mem[(size_t)n*WMEM + w] = v;
    }
#pragma unroll
    for (int o=4;o;o>>=1) ss += __shfl_xor_sync(0xffffffffu, ss, o);
    float inv = 1.f/fmaxf(sqrtf(ss), 1e-12f);
#pragma unroll
    for (int j=0;j<16;++j)
        g_mhat[(size_t)n*WMEM + wq*16 + j] = nv[j]*inv;
}
__global__ void zero_rv() {
    int idx = blockIdx.x*256 + threadIdx.x;
    if (idx < B_*WMEM) g_rv[idx] = 0.f;
}
// rv[b,w] += sum over this block's 128 n of rw[b,n]*mem[n,w]
__global__ void __launch_bounds__(256) rv_gemm() {
    __shared__ __align__(16) float rs[16][132];
    __shared__ __align__(16) float ms[16][132];
    int tid = threadIdx.x;
    int tx = tid & 15, ty = tid >> 4;
    int nbase = blockIdx.x*128;
    float acc[8][8];
#pragma unroll
    for (int i=0;i<8;++i)
#pragma unroll
        for (int j=0;j<8;++j) acc[i][j]=0.f;
    for (int kt=0; kt<8; ++kt) {
        int n0 = nbase + kt*16;
#pragma unroll
        for (int i=0;i<8;++i) {
            int l = tid + i*256; int b = l>>4, k = l&15;
            rs[k][b] = g_rw[(size_t)b*NMEM + n0 + k];
        }
#pragma unroll
        for (int i=0;i<8;++i) {
            int l = tid + i*256; int k = l>>7, w = l&127;
            ms[k][w] = g_mem[(size_t)(n0+k)*WMEM + w];
        }
        __syncthreads();
#pragma unroll
        for (int k=0;k<16;++k) {
            float4 b0 = *reinterpret_cast<const float4*>(&rs[k][ty*8]);
            float4 b1 = *reinterpret_cast<const float4*>(&rs[k][ty*8+4]);
            float4 w0 = *reinterpret_cast<const float4*>(&ms[k][tx*8]);
            float4 w1 = *reinterpret_cast<const float4*>(&ms[k][tx*8+4]);
            float br[8] = {b0.x,b0.y,b0.z,b0.w,b1.x,b1.y,b1.z,b1.w};
            float wr[8] = {w0.x,w0.y,w0.z,w0.w,w1.x,w1.y,w1.z,w1.w};
#pragma unroll
            for (int i=0;i<8;++i)
#pragma unroll
                for (int j=0;j<8;++j) acc[i][j]=fmaf(br[i],wr[j],acc[i][j]);
        }
        __syncthreads();
    }
#pragma unroll
    for (int i=0;i<8;++i)
#pragma unroll
        for (int j=0;j<8;++j)
            atomicAdd(&g_rv[(size_t)(ty*8+i)*WMEM + tx*8+j], acc[i][j]);
}

// ==================================================================================
extern "C" void kernel_launch(void* const* d_in, const int* in_sizes, int n_in,
                              void* d_out, int out_size)
{
    const float* x      = (const float*)d_in[0];
    const float* memory = (const float*)d_in[1];
    const float* Wih    = (const float*)d_in[2];
    const float* Whh    = (const float*)d_in[3];
    const float* bih    = (const float*)d_in[4];
    const float* bhh    = (const float*)d_in[5];
    const float* Wout   = (const float*)d_in[6];
    const float* bout   = (const float*)d_in[7];
    const float* rkW    = (const float*)d_in[8];
    const float* rkb    = (const float*)d_in[9];
    const float* rbW    = (const float*)d_in[10];
    const float* rbb    = (const float*)d_in[11];
    const float* rgW    = (const float*)d_in[12];
    const float* rgb    = (const float*)d_in[13];
    const float* wkW    = (const float*)d_in[14];
    const float* wkb    = (const float*)d_in[15];
    const float* wbW    = (const float*)d_in[16];
    const float* wbb    = (const float*)d_in[17];
    const float* wgW    = (const float*)d_in[18];
    const float* wgb    = (const float*)d_in[19];
    const float* erW    = (const float*)d_in[20];
    const float* erb    = (const float*)d_in[21];
    const float* adW    = (const float*)d_in[22];
    const float* adb    = (const float*)d_in[23];
    const float* pW     = (const float*)d_in[24];
    const float* pb     = (const float*)d_in[25];
    float* out = (float*)d_out;

    float *p_h,*p_rv,*p_gates,*p_Wf,*p_P,*p_khat,*p_mhat,*p_sim,*p_HWcat,*p_WoutT;
    cudaGetSymbolAddress((void**)&p_h,     g_h);
    cudaGetSymbolAddress((void**)&p_rv,    g_rv);
    cudaGetSymbolAddress((void**)&p_gates, g_gates);
    cudaGetSymbolAddress((void**)&p_Wf,    g_Wf);
    cudaGetSymbolAddress((void**)&p_P,     g_P);
    cudaGetSymbolAddress((void**)&p_khat,  g_khat);
    cudaGetSymbolAddress((void**)&p_mhat,  g_mhat);
    cudaGetSymbolAddress((void**)&p_sim,   g_sim);
    cudaGetSymbolAddress((void**)&p_HWcat, g_HWcat);
    cudaGetSymbolAddress((void**)&p_WoutT, g_WoutT);

    const int BIG = 1<<30;

    // -------- preamble (re-runs every replay; fully deterministic) --------
    init_state<<<(B_*NMEM)/256, 256>>>();
    bsum_k<<<16, 256>>>(bih, bhh);
    gather_HWcat<<<(WF_M*WF_K)/256, 256>>>(rkW,rbW,rgW,wkW,wbW,wgW,erW,adW,pW);
    transpose_Wout<<<(H_*WF_K)/256, 256>>>(Wout);
    // Wf = HWcat @ Wout  (NT vs WoutT):  [1152 x 1024], K=912
    gemm_nt<0><<<dim3(16, 9, 1), 256>>>(
        p_HWcat, WF_K, BIG, nullptr,0,0, nullptr,0,
        p_WoutT, WF_K, BIG, nullptr,0,
        p_Wf, H_, H_, WF_K/16, WF_K/16, nullptr);
    bf_k<<<CP, 128>>>(bout, rkb,rbb,rgb, wkb,wbb,wgb, erb,adb,pb);
    norm_mhat<<<NMEM/8, 256>>>(memory);

    // -------- 32 sequential steps --------
    for (int t = 0; t < S_; ++t) {
        // gates = [x_t | rv | h] @ [Wih | Whh].T + (bih+bhh)
        preinit_gates<<<(B_*G4H)/256, 256>>>();
        gemm_nt<2><<<dim3(G4H/64, 1, 4), 256>>>(
            x + (size_t)t*IN_, S_*IN_, IN_,     // A0: x_t  (row stride S*IN)
            p_rv, WMEM, WMEM,                   // A1: rv
            p_h,  H_,                           // A2: h
            Wih, IN_+WMEM, IN_+WMEM,            // B0: Wih [4096 x 640]
            Whh, H_,                            // B1: Whh [4096 x 1024]
            p_gates, G4H, G4H, 1664/16, 26, nullptr);
        lstm_pw<<<(B_*H_)/256, 256>>>();

        // P = h @ Wf.T + bf   [128 x 1028], K=1024, split-K z=8
        preinit_P<<<(B_*CP+255)/256, 256>>>();
        gemm_nt<2><<<dim3((CP+63)/64, 1, 8), 256>>>(
            p_h, H_, BIG, nullptr,0,0, nullptr,0,
            p_Wf, H_, BIG, nullptr,0,
            p_P, CP, CP, H_/16, 8, nullptr);
        head_pw<<<B_, 128>>>(out, t);

        // sim = khat @ mhat.T   [256 x 16384], K=128
        gemm_nt<0><<<dim3(NMEM/64, 2, 1), 256>>>(
            p_khat, WMEM, BIG, nullptr,0,0, nullptr,0,
            p_mhat, WMEM, BIG, nullptr,0,
            p_sim, NMEM, NMEM, WMEM/16, WMEM/16, nullptr);
        softmax_interp<<<2*B_, 256>>>();

        mem_write<<<NMEM/32, 256>>>();

        zero_rv<<<(B_*WMEM)/256, 256>>>();
        rv_gemm<<<NMEM/128, 256>>>();
    }
}

// round 5
// speedup vs baseline: 3.4652x; 3.4652x over previous
#include <cuda_runtime.h>
#include <math.h>
#include <stdint.h>

#define B_   128
#define S_   32
#define IN_  512
#define H_   1024
#define OUT_ 512
#define NMEM 16384
#define WMEM 128
#define CDIM 899
#define G4H  4096
#define CP   1028
#define WF_M 1152
#define WF_K 912
#define GZ   8          // split-K parts for gates GEMM

// ---------------- scratch ----------------
__device__ float g_mem [NMEM*WMEM];
__device__ float g_mhat[NMEM*WMEM];
__device__ float g_E   [NMEM*WMEM];
__device__ float g_A   [NMEM*WMEM];
__device__ float g_h   [B_*H_];
__device__ float g_c   [B_*H_];
__device__ float g_rv  [B_*WMEM];
__device__ float g_rw  [B_*NMEM];
__device__ float g_ww  [B_*NMEM];
__device__ float g_gparts[GZ*B_*G4H];
__device__ float g_P   [B_*CP];
__device__ float g_khat[2*B_*WMEM];
__device__ float g_gamma[2*B_];
__device__ float g_er  [B_*WMEM];
__device__ float g_ad  [B_*WMEM];
__device__ float g_sim [2*B_*NMEM];
__device__ float g_bsum[G4H];
__device__ float g_HWcat[WF_M*WF_K];
__device__ float g_WoutT[H_*WF_K];
__device__ float g_Wf  [WF_M*H_];
__device__ float g_bf  [CP];

__device__ __forceinline__ float sigmoidf_(float x){ return 1.f/(1.f+__expf(-x)); }
__device__ __forceinline__ float softplusf_(float x){ return x>20.f ? x : log1pf(__expf(x)); }
__device__ __forceinline__ uint32_t f2tf32(float f){
    uint32_t u; asm("cvt.rna.tf32.f32 %0, %1;" : "=r"(u) : "f"(f)); return u;
}
__device__ __forceinline__ void mma_tf32(float c[4], const uint32_t a[4], uint32_t b0, uint32_t b1){
    asm volatile("mma.sync.aligned.m16n8k8.row.col.f32.tf32.tf32.f32 "
        "{%0,%1,%2,%3}, {%4,%5,%6,%7}, {%8,%9}, {%0,%1,%2,%3};"
        : "+f"(c[0]), "+f"(c[1]), "+f"(c[2]), "+f"(c[3])
        : "r"(a[0]), "r"(a[1]), "r"(a[2]), "r"(a[3]), "r"(b0), "r"(b1));
}

// ===================== tf32 MMA NT GEMM =====================
// C[m,n] (op)= sum_k A[m,k]*B[n,k].  Block tile 128x128, 8 warps (4m x 2n),
// warp tile 32x64 via m16n8k8.  A up to 3 row-major segments along k; B up to 2.
// TRA: A stored [k][m] (single segment). TRB: B stored [k][n] (single segment).
// MODE 0: overwrite C + blockIdx.z*czstride.  MODE 1: atomicAdd into C.
// All M, N must be multiples of 128 (no guards).
#define SP 20
template<int MODE, int TRA, int TRB>
__global__ void __launch_bounds__(256) mma_nt(
    const float* __restrict__ A0,int alda0,int alen0,
    const float* __restrict__ A1,int alda1,int alen1,
    const float* __restrict__ A2,int alda2,
    const float* __restrict__ B0,int blda0,int blen0,
    const float* __restrict__ B1,int blda1,
    float* __restrict__ C,int ldc,
    int ktTotal,int ktPerZ, size_t czstride)
{
    __shared__ uint32_t As[128*SP];
    __shared__ uint32_t Bs[128*SP];
    const int tid = threadIdx.x;
    const int lane = tid & 31, wid = tid >> 5;
    const int wm = wid & 3, wn = wid >> 2;
    const int lr = lane >> 2, lc = lane & 3;
    const int n0 = blockIdx.x*128, m0 = blockIdx.y*128;
    int kb = blockIdx.z*ktPerZ;
    int ke = kb + ktPerZ; if (ke > ktTotal) ke = ktTotal;

    float acc[2][8][4];
#pragma unroll
    for (int i=0;i<2;++i)
#pragma unroll
        for (int j=0;j<8;++j)
#pragma unroll
            for (int q=0;q<4;++q) acc[i][j][q]=0.f;

    for (int kt = kb; kt < ke; ++kt) {
        const int kk0 = kt*16;
        const float* Ap; int alda, ak;
        if      (kk0 <  alen0)       { Ap=A0; alda=alda0; ak=kk0; }
        else if (kk0 <  alen0+alen1) { Ap=A1; alda=alda1; ak=kk0-alen0; }
        else                         { Ap=A2; alda=alda2; ak=kk0-alen0-alen1; }
        const float* Bp; int blda, bk;
        if (kk0 < blen0) { Bp=B0; blda=blda0; bk=kk0; }
        else             { Bp=B1; blda=blda1; bk=kk0-blen0; }

#pragma unroll
        for (int i=0;i<8;++i) {
            int l = tid + i*256;
            int am, akk;
            if (TRA) { am = l & 127; akk = l >> 7; }
            else     { am = l >> 4;  akk = l & 15; }
            float v = TRA ? Ap[(size_t)(ak+akk)*alda + m0 + am]
                          : Ap[(size_t)(m0+am)*alda + ak + akk];
            As[am*SP + akk] = f2tf32(v);
        }
#pragma unroll
        for (int i=0;i<8;++i) {
            int l = tid + i*256;
            int bn, bkk;
            if (TRB) { bn = l & 127; bkk = l >> 7; }
            else     { bn = l >> 4;  bkk = l & 15; }
            float v = TRB ? Bp[(size_t)(bk+bkk)*blda + n0 + bn]
                          : Bp[(size_t)(n0+bn)*blda + bk + bkk];
            Bs[bn*SP + bkk] = f2tf32(v);
        }
        __syncthreads();
#pragma unroll
        for (int h=0; h<2; ++h) {
            const int k8 = h*8;
            uint32_t af[2][4];
#pragma unroll
            for (int ma=0; ma<2; ++ma) {
                int rb = (wm*32 + ma*16 + lr)*SP + k8 + lc;
                af[ma][0] = As[rb];
                af[ma][1] = As[rb + 8*SP];
                af[ma][2] = As[rb + 4];
                af[ma][3] = As[rb + 8*SP + 4];
            }
#pragma unroll
            for (int nb=0; nb<8; ++nb) {
                int rb = (wn*64 + nb*8 + lr)*SP + k8 + lc;
                uint32_t b0 = Bs[rb], b1 = Bs[rb + 4];
#pragma unroll
                for (int ma=0; ma<2; ++ma) mma_tf32(acc[ma][nb], af[ma], b0, b1);
            }
        }
        __syncthreads();
    }

    float* Cz = C + (size_t)blockIdx.z*czstride;
#pragma unroll
    for (int ma=0; ma<2; ++ma) {
        int row = m0 + wm*32 + ma*16 + lr;
#pragma unroll
        for (int nb=0; nb<8; ++nb) {
            int col = n0 + wn*64 + nb*8 + 2*lc;
            if (MODE==0) {
                *reinterpret_cast<float2*>(&Cz[(size_t)row*ldc + col])     = make_float2(acc[ma][nb][0], acc[ma][nb][1]);
                *reinterpret_cast<float2*>(&Cz[(size_t)(row+8)*ldc + col]) = make_float2(acc[ma][nb][2], acc[ma][nb][3]);
            } else {
                atomicAdd(&Cz[(size_t)row*ldc + col],       acc[ma][nb][0]);
                atomicAdd(&Cz[(size_t)row*ldc + col + 1],   acc[ma][nb][1]);
                atomicAdd(&Cz[(size_t)(row+8)*ldc + col],   acc[ma][nb][2]);
                atomicAdd(&Cz[(size_t)(row+8)*ldc + col+1], acc[ma][nb][3]);
            }
        }
    }
}

// ===================== fp32 FFMA GEMM (preamble Wf + per-step P) =====================
template<int MODE>
__global__ void __launch_bounds__(256) gemm_nt(
    const float* __restrict__ A0,int alda0,
    const float* __restrict__ B0,int blda0,
    float* __restrict__ C,int ldc,int Nn,
    int ktotal,int ktPerZ)
{
    __shared__ __align__(16) float As[16][132];
    __shared__ __align__(16) float Bs[16][68];
    int tid = threadIdx.x;
    int tx = tid & 15, ty = tid >> 4;
    int n0 = blockIdx.x*64, m0 = blockIdx.y*128;
    int kb = blockIdx.z*ktPerZ;
    int ke = kb + ktPerZ; if (ke > ktotal) ke = ktotal;
    float acc[8][4];
#pragma unroll
    for (int i=0;i<8;++i)
#pragma unroll
        for (int j=0;j<4;++j) acc[i][j]=0.f;
    for (int kt=kb; kt<ke; ++kt) {
        int kk0 = kt*16;
#pragma unroll
        for (int i=0;i<8;++i) {
            int l = tid + i*256; int m = l>>4, k = l&15;
            As[k][m] = A0[(size_t)(m0+m)*alda0 + kk0 + k];
        }
#pragma unroll
        for (int i=0;i<4;++i) {
            int l = tid + i*256; int n = l>>4, k = l&15;
            Bs[k][n] = (n0+n < Nn) ? B0[(size_t)(n0+n)*blda0 + kk0 + k] : 0.f;
        }
        __syncthreads();
#pragma unroll
        for (int k=0;k<16;++k) {
            float4 a0 = *reinterpret_cast<const float4*>(&As[k][ty*8]);
            float4 a1 = *reinterpret_cast<const float4*>(&As[k][ty*8+4]);
            float4 b0 = *reinterpret_cast<const float4*>(&Bs[k][tx*4]);
            float ar[8] = {a0.x,a0.y,a0.z,a0.w,a1.x,a1.y,a1.z,a1.w};
            float br[4] = {b0.x,b0.y,b0.z,b0.w};
#pragma unroll
            for (int i=0;i<8;++i)
#pragma unroll
                for (int j=0;j<4;++j) acc[i][j]=fmaf(ar[i],br[j],acc[i][j]);
        }
        __syncthreads();
    }
#pragma unroll
    for (int i=0;i<8;++i) {
        int m = m0 + ty*8 + i;
#pragma unroll
        for (int j=0;j<4;++j) {
            int n = n0 + tx*4 + j;
            if (n < Nn) {
                size_t idx = (size_t)m*ldc + n;
                if (MODE==0) C[idx] = acc[i][j];
                else         atomicAdd(&C[idx], acc[i][j]);
            }
        }
    }
}

// ---------------- preamble ----------------
__global__ void init_state() {
    int idx = blockIdx.x*256 + threadIdx.x;          // B_*NMEM threads
    g_rw[idx] = 1.f/NMEM;
    if (idx < B_*H_)   { g_h[idx]=0.f; g_c[idx]=0.f; }
    if (idx < B_*WMEM)   g_rv[idx]=0.f;
}
__global__ void bsum_k(const float* __restrict__ bih, const float* __restrict__ bhh) {
    int i = blockIdx.x*256 + threadIdx.x;
    if (i < G4H) g_bsum[i] = bih[i]+bhh[i];
}
__global__ void gather_HWcat(
    const float* __restrict__ rkW, const float* __restrict__ rbW, const float* __restrict__ rgW,
    const float* __restrict__ wkW, const float* __restrict__ wbW, const float* __restrict__ wgW,
    const float* __restrict__ erW, const float* __restrict__ adW, const float* __restrict__ pW)
{
    int idx = blockIdx.x*256 + threadIdx.x;          // WF_M*WF_K exact
    int j = idx / WF_K, cx = idx % WF_K;
    float v = 0.f;
    if (cx < CDIM) {
        if      (j < 128)  v = rkW[(size_t)j*CDIM + cx];
        else if (j == 128) v = rbW[cx];
        else if (j == 129) v = rgW[cx];
        else if (j < 258)  v = wkW[(size_t)(j-130)*CDIM + cx];
        else if (j == 258) v = wbW[cx];
        else if (j == 259) v = wgW[cx];
        else if (j < 388)  v = erW[(size_t)(j-260)*CDIM + cx];
        else if (j < 516)  v = adW[(size_t)(j-388)*CDIM + cx];
        else if (j < CP)   { if (cx < OUT_) v = pW[(size_t)(j-516)*OUT_ + cx]; }
    }
    g_HWcat[idx] = v;
}
__global__ void transpose_Wout(const float* __restrict__ Wout) {
    int idx = blockIdx.x*256 + threadIdx.x;          // H_*WF_K exact
    int h = idx / WF_K, c = idx % WF_K;
    g_WoutT[idx] = (c < CDIM) ? Wout[(size_t)c*H_ + h] : 0.f;
}
__global__ void __launch_bounds__(128) bf_k(
    const float* __restrict__ bout,
    const float* __restrict__ rkb, const float* __restrict__ rbb, const float* __restrict__ rgb,
    const float* __restrict__ wkb, const float* __restrict__ wbb, const float* __restrict__ wgb,
    const float* __restrict__ erb, const float* __restrict__ adb, const float* __restrict__ pb)
{
    int j = blockIdx.x, tid = threadIdx.x;
    float s = 0.f;
    for (int c = tid; c < CDIM; c += 128) s += g_HWcat[(size_t)j*WF_K + c] * bout[c];
#pragma unroll
    for (int o=16;o;o>>=1) s += __shfl_xor_sync(0xffffffffu, s, o);
    __shared__ float red[4];
    if ((tid&31)==0) red[tid>>5] = s;
    __syncthreads();
    if (tid==0) {
        float t = red[0]+red[1]+red[2]+red[3], hb;
        if      (j < 128)  hb = rkb[j];
        else if (j == 128) hb = rbb[0];
        else if (j == 129) hb = rgb[0];
        else if (j < 258)  hb = wkb[j-130];
        else if (j == 258) hb = wbb[0];
        else if (j == 259) hb = wgb[0];
        else if (j < 388)  hb = erb[j-260];
        else if (j < 516)  hb = adb[j-388];
        else               hb = pb[j-516];
        g_bf[j] = t + hb;
    }
}
__global__ void __launch_bounds__(256) norm_mhat(const float* __restrict__ memin) {
    int warp = threadIdx.x>>5, lane = threadIdx.x&31;
    int r = blockIdx.x*8 + warp;
    float v[4]; float ss = 0.f;
#pragma unroll
    for (int i=0;i<4;++i) { v[i] = memin[(size_t)r*WMEM + lane + 32*i]; ss += v[i]*v[i]; }
#pragma unroll
    for (int o=16;o;o>>=1) ss += __shfl_xor_sync(0xffffffffu, ss, o);
    float inv = 1.f/fmaxf(sqrtf(ss), 1e-12f);
#pragma unroll
    for (int i=0;i<4;++i) {
        g_mem [(size_t)r*WMEM + lane + 32*i] = v[i];
        g_mhat[(size_t)r*WMEM + lane + 32*i] = v[i]*inv;
    }
}

// ---------------- per-step ----------------
__global__ void __launch_bounds__(256) lstm_pw() {
    int idx = blockIdx.x*256 + threadIdx.x;          // B_*H_ exact
    int b = idx >> 10, j = idx & 1023;
    float i_ = g_bsum[j], f_ = g_bsum[j+1024], gg = g_bsum[j+2048], o_ = g_bsum[j+3072];
#pragma unroll
    for (int p=0; p<GZ; ++p) {
        const float* g = g_gparts + (size_t)p*(B_*G4H) + (size_t)b*G4H;
        i_ += g[j]; f_ += g[j+1024]; gg += g[j+2048]; o_ += g[j+3072];
    }
    float cv = g_c[idx];
    cv = sigmoidf_(f_)*cv + sigmoidf_(i_)*tanhf(gg);
    g_c[idx] = cv;
    g_h[idx] = sigmoidf_(o_)*tanhf(cv);
}
__global__ void preinit_P() {
    int idx = blockIdx.x*256 + threadIdx.x;
    if (idx < B_*CP) g_P[idx] = g_bf[idx % CP];
}
__global__ void __launch_bounds__(128) head_pw(float* __restrict__ out, int t) {
    int b = blockIdx.x, tid = threadIdx.x;
    const float* p = g_P + (size_t)b*CP;
    __shared__ float red[4];
    __shared__ float bnr, bnw;
    float rk = p[tid], wk = p[130+tid];
    float s = rk*rk;
#pragma unroll
    for (int o=16;o;o>>=1) s += __shfl_xor_sync(0xffffffffu, s, o);
    if ((tid&31)==0) red[tid>>5] = s;
    __syncthreads();
    if (tid==0) bnr = sqrtf(red[0]+red[1]+red[2]+red[3]);
    __syncthreads();
    s = wk*wk;
#pragma unroll
    for (int o=16;o;o>>=1) s += __shfl_xor_sync(0xffffffffu, s, o);
    if ((tid&31)==0) red[tid>>5] = s;
    __syncthreads();
    if (tid==0) bnw = sqrtf(red[0]+red[1]+red[2]+red[3]);
    __syncthreads();

    float rbeta = softplusf_(p[128]);
    float wbeta = softplusf_(p[258]);
    g_khat[(size_t)b*WMEM + tid]      = rbeta * rk / fmaxf(bnr, 1e-12f);
    g_khat[(size_t)(B_+b)*WMEM + tid] = wbeta * wk / fmaxf(bnw, 1e-12f);
    if (tid==0) {
        g_gamma[b]    = 1.f + softplusf_(p[129]);
        g_gamma[B_+b] = 1.f + softplusf_(p[259]);
    }
    g_er[(size_t)b*WMEM + tid] = sigmoidf_(p[260+tid]);
    g_ad[(size_t)b*WMEM + tid] = tanhf(p[388+tid]);
#pragma unroll
    for (int j=tid; j<OUT_; j+=128)
        out[((size_t)b*S_ + t)*OUT_ + j] = p[516+j];
}
__global__ void __launch_bounds__(256) softmax_interp() {
    int row = blockIdx.x, tid = threadIdx.x;
    const float* sr = g_sim + (size_t)row*NMEM;
    __shared__ float red[8];
    __shared__ float bmax, bsum2;
    float mx = -3.4e38f;
    for (int n=tid; n<NMEM; n+=256) mx = fmaxf(mx, sr[n]);
#pragma unroll
    for (int o=16;o;o>>=1) mx = fmaxf(mx, __shfl_xor_sync(0xffffffffu, mx, o));
    if ((tid&31)==0) red[tid>>5] = mx;
    __syncthreads();
    if (tid==0) { float t=red[0]; for (int i=1;i<8;++i) t=fmaxf(t,red[i]); bmax=t; }
    __syncthreads();
    float sum = 0.f;
    for (int n=tid; n<NMEM; n+=256) sum += __expf(sr[n]-bmax);
#pragma unroll
    for (int o=16;o;o>>=1) sum += __shfl_xor_sync(0xffffffffu, sum, o);
    if ((tid&31)==0) red[tid>>5] = sum;
    __syncthreads();
    if (tid==0) { float t=0.f; for (int i=0;i<8;++i) t+=red[i]; bsum2=t; }
    __syncthreads();
    float inv = 1.f/bsum2;
    float g = g_gamma[row];
    if (row < B_) {
        float* dst = g_rw + (size_t)row*NMEM;
        for (int n=tid; n<NMEM; n+=256) {
            float w = __expf(sr[n]-bmax)*inv;
            dst[n] = g*w + (1.f-g)*dst[n];
        }
    } else {
        float* dst = g_ww + (size_t)(row-B_)*NMEM;
        const float u = 1.f/NMEM;
        for (int n=tid; n<NMEM; n+=256) {
            float w = __expf(sr[n]-bmax)*inv;
            dst[n] = g*w + (1.f-g)*u;
        }
    }
}
// mem = mem*(1-E) + A, plus mhat renorm.  One warp per memory row.
__global__ void __launch_bounds__(256) mem_update() {
    int warp = threadIdx.x>>5, lane = threadIdx.x&31;
    int r = blockIdx.x*8 + warp;
    float v[4]; float ss = 0.f;
#pragma unroll
    for (int i=0;i<4;++i) {
        size_t idx = (size_t)r*WMEM + lane + 32*i;
        float m = g_mem[idx];
        float vv = m*(1.f - g_E[idx]) + g_A[idx];
        v[i] = vv; ss += vv*vv;
        g_mem[idx] = vv;
    }
#pragma unroll
    for (int o=16;o;o>>=1) ss += __shfl_xor_sync(0xffffffffu, ss, o);
    float inv = 1.f/fmaxf(sqrtf(ss), 1e-12f);
#pragma unroll
    for (int i=0;i<4;++i)
        g_mhat[(size_t)r*WMEM + lane + 32*i] = v[i]*inv;
}
__global__ void zero_rv() {
    int idx = blockIdx.x*256 + threadIdx.x;
    if (idx < B_*WMEM) g_rv[idx] = 0.f;
}

// ==================================================================================
extern "C" void kernel_launch(void* const* d_in, const int* in_sizes, int n_in,
                              void* d_out, int out_size)
{
    const float* x      = (const float*)d_in[0];
    const float* memory = (const float*)d_in[1];
    const float* Wih    = (const float*)d_in[2];
    const float* Whh    = (const float*)d_in[3];
    const float* bih    = (const float*)d_in[4];
    const float* bhh    = (const float*)d_in[5];
    const float* Wout   = (const float*)d_in[6];
    const float* bout   = (const float*)d_in[7];
    const float* rkW    = (const float*)d_in[8];
    const float* rkb    = (const float*)d_in[9];
    const float* rbW    = (const float*)d_in[10];
    const float* rbb    = (const float*)d_in[11];
    const float* rgW    = (const float*)d_in[12];
    const float* rgb    = (const float*)d_in[13];
    const float* wkW    = (const float*)d_in[14];
    const float* wkb    = (const float*)d_in[15];
    const float* wbW    = (const float*)d_in[16];
    const float* wbb    = (const float*)d_in[17];
    const float* wgW    = (const float*)d_in[18];
    const float* wgb    = (const float*)d_in[19];
    const float* erW    = (const float*)d_in[20];
    const float* erb    = (const float*)d_in[21];
    const float* adW    = (const float*)d_in[22];
    const float* adb    = (const float*)d_in[23];
    const float* pW     = (const float*)d_in[24];
    const float* pb     = (const float*)d_in[25];
    float* out = (float*)d_out;

    float *p_h,*p_rv,*p_gparts,*p_Wf,*p_P,*p_khat,*p_mhat,*p_sim,*p_HWcat,*p_WoutT;
    float *p_rw,*p_ww,*p_er,*p_ad,*p_E,*p_A,*p_mem;
    cudaGetSymbolAddress((void**)&p_h,      g_h);
    cudaGetSymbolAddress((void**)&p_rv,     g_rv);
    cudaGetSymbolAddress((void**)&p_gparts, g_gparts);
    cudaGetSymbolAddress((void**)&p_Wf,     g_Wf);
    cudaGetSymbolAddress((void**)&p_P,      g_P);
    cudaGetSymbolAddress((void**)&p_khat,   g_khat);
    cudaGetSymbolAddress((void**)&p_mhat,   g_mhat);
    cudaGetSymbolAddress((void**)&p_sim,    g_sim);
    cudaGetSymbolAddress((void**)&p_HWcat,  g_HWcat);
    cudaGetSymbolAddress((void**)&p_WoutT,  g_WoutT);
    cudaGetSymbolAddress((void**)&p_rw,     g_rw);
    cudaGetSymbolAddress((void**)&p_ww,     g_ww);
    cudaGetSymbolAddress((void**)&p_er,     g_er);
    cudaGetSymbolAddress((void**)&p_ad,     g_ad);
    cudaGetSymbolAddress((void**)&p_E,      g_E);
    cudaGetSymbolAddress((void**)&p_A,      g_A);
    cudaGetSymbolAddress((void**)&p_mem,    g_mem);

    // -------- preamble (re-runs every replay; fully deterministic) --------
    init_state<<<(B_*NMEM)/256, 256>>>();
    bsum_k<<<16, 256>>>(bih, bhh);
    gather_HWcat<<<(WF_M*WF_K)/256, 256>>>(rkW,rbW,rgW,wkW,wbW,wgW,erW,adW,pW);
    transpose_Wout<<<(H_*WF_K)/256, 256>>>(Wout);
    // Wf = HWcat @ Wout  : [1152 x 1024], K=912  (fp32)
    gemm_nt<0><<<dim3(16, 9, 1), 256>>>(
        p_HWcat, WF_K, p_WoutT, WF_K, p_Wf, H_, H_, WF_K/16, WF_K/16);
    bf_k<<<CP, 128>>>(bout, rkb,rbb,rgb, wkb,wbb,wgb, erb,adb,pb);
    norm_mhat<<<NMEM/8, 256>>>(memory);

    // -------- 32 sequential steps --------
    for (int t = 0; t < S_; ++t) {
        // gates parts = [x_t | rv | h] @ [Wih | Whh].T   (tf32, split-K -> GZ parts)
        mma_nt<0,0,0><<<dim3(G4H/128, 1, GZ), 256>>>(
            x + (size_t)t*IN_, S_*IN_, IN_,
            p_rv, WMEM, WMEM,
            p_h,  H_,
            Wih, IN_+WMEM, IN_+WMEM,
            Whh, H_,
            p_gparts, G4H, 1664/16, (1664/16)/GZ, (size_t)B_*G4H);
        lstm_pw<<<(B_*H_)/256, 256>>>();

        // P = h @ Wf.T + bf   [128 x 1028], K=1024 (fp32, split-K atomic)
        preinit_P<<<(B_*CP+255)/256, 256>>>();
        gemm_nt<2><<<dim3((CP+63)/64, 1, 8), 256>>>(
            p_h, H_, p_Wf, H_, p_P, CP, CP, H_/16, 8);
        head_pw<<<B_, 128>>>(out, t);

        // sim = khat @ mhat.T   [256 x 16384], K=128 (tf32)
        mma_nt<0,0,0><<<dim3(NMEM/128, 2, 1), 256>>>(
            p_khat, WMEM, 1<<30, nullptr,0,0, nullptr,0,
            p_mhat, WMEM, 1<<30, nullptr,0,
            p_sim, NMEM, WMEM/16, WMEM/16, 0);
        softmax_interp<<<2*B_, 256>>>();

        // E = ww^T @ er  and  A = ww^T @ ad   [16384 x 128], K=128 (tf32)
        mma_nt<0,1,1><<<dim3(1, NMEM/128, 1), 256>>>(
            p_ww, NMEM, 1<<30, nullptr,0,0, nullptr,0,
            p_er, WMEM, 1<<30, nullptr,0,
            p_E, WMEM, WMEM/16, WMEM/16, 0);
        mma_nt<0,1,1><<<dim3(1, NMEM/128, 1), 256>>>(
            p_ww, NMEM, 1<<30, nullptr,0,0, nullptr,0,
            p_ad, WMEM, 1<<30, nullptr,0,
            p_A, WMEM, WMEM/16, WMEM/16, 0);
        mem_update<<<NMEM/8, 256>>>();

        // rv = rw @ mem   [128 x 128], K=16384 (tf32, split-K atomic)
        zero_rv<<<(B_*WMEM)/256, 256>>>();
        mma_nt<1,0,1><<<dim3(1, 1, 128), 256>>>(
            p_rw, NMEM, 1<<30, nullptr,0,0, nullptr,0,
            p_mem, WMEM, 1<<30, nullptr,0,
            p_rv, WMEM, NMEM/16, (NMEM/16)/128, 0);
    }
}